// round 3
// baseline (speedup 1.0000x reference)
#include <cuda_runtime.h>

// Problem constants
#define NN   64
#define CC   64
#define TP   300
#define VV   25
#define OO   64
#define NA   3
#define TT   10            // t-rows per block tile
#define TWC  250           // TT*VV columns per tile
#define XSTR 260           // padded smem row stride (mult of 4, not mult of 32)
#define ASTR 28            // padded A row (mult of 4)
#define APITCH (VV*ASTR)   // 700
#define NTOT (64*300*25)   // elements per channel for BN stats

// Scratch (static device allocations are the sanctioned workaround)
__device__ float g_y[(size_t)NN*OO*TP*VV];   // pre-BN activations, 122.88 MB
__device__ float g_sum[OO];
__device__ float g_sumsq[OO];
__device__ float g_scale[OO];
__device__ float g_shift[OO];

__global__ void zero_stats_kernel() {
    g_sum[threadIdx.x]   = 0.f;
    g_sumsq[threadIdx.x] = 0.f;
}

__global__ __launch_bounds__(256) void compute_kernel(
    const float* __restrict__ x,
    const float* __restrict__ A,
    const float* __restrict__ W)
{
    extern __shared__ float smem[];
    float* As = smem;                    // NA*APITCH = 2100 floats (zero-padded rows)
    float* Wt = As + NA*APITCH;          // 12288 floats, [a][c][o]
    float* xs = Wt + NA*4096;            // CC*XSTR
    float* zs = xs + CC*XSTR;            // CC*XSTR

    const int tid = threadIdx.x;
    const int tb  = blockIdx.x;          // 0..29 (t tile)
    const int n   = blockIdx.y;          // 0..63

    // Load A with row padding (pad cols 25..27 = 0)
    for (int i = tid; i < NA*APITCH; i += 256) {
        int a = i / APITCH; int r = i - a*APITCH;
        int v = r / ASTR;   int w = r - v*ASTR;
        As[i] = (w < VV) ? A[(a*VV + v)*VV + w] : 0.f;
    }
    // Load W transposed: Wt[a][c][o] = W[a][o][c]  (writes coalesced, reads L2-hot)
    for (int i = tid; i < NA*4096; i += 256) {
        int a = i >> 12; int r = i & 4095;
        int c = r >> 6;  int o = r & 63;
        Wt[i] = W[a*4096 + o*64 + c];
    }
    // Load x tile: xs[c][tw], tw = t_local*25 + v (250 contiguous floats per c)
    {
        const float* xsrc = x + (size_t)(n*CC)*7500 + (size_t)tb*TWC;
        for (int i = tid; i < CC*TWC; i += 256) {
            int c = i / TWC; int r = i - c*TWC;
            xs[c*XSTR + r] = xsrc[(size_t)c*7500 + r];
        }
    }
    // Zero zs tail columns [250, 260) (float4 reads in stage2 touch up to 255)
    for (int i = tid; i < CC*(XSTR-TWC); i += 256) {
        int c = i / (XSTR-TWC); int r = i - c*(XSTR-TWC);
        zs[c*XSTR + TWC + r] = 0.f;
    }
    __syncthreads();

    const int og  = (tid >> 5) << 3;     // 8-o group; all threads in a warp share og
    const int twb = (tid & 31) << 3;     // 8-tw group

    float acc[8][8];
    #pragma unroll
    for (int i = 0; i < 8; i++)
        #pragma unroll
        for (int j = 0; j < 8; j++) acc[i][j] = 0.f;

    for (int a = 0; a < NA; a++) {
        // ---- stage 1: zs[c][t*25+w] = sum_v xs[c][t*25+v] * A[a][v][w] ----
        for (int p = tid; p < CC*TT; p += 256) {
            int c = p / TT; int t = p - c*TT;
            const float* xrow = xs + c*XSTR + t*VV;
            float zacc[ASTR];
            #pragma unroll
            for (int k = 0; k < ASTR; k++) zacc[k] = 0.f;
            #pragma unroll 5
            for (int v = 0; v < VV; v++) {
                float xv = xrow[v];
                const float4* a4 = (const float4*)(As + a*APITCH + v*ASTR);
                #pragma unroll
                for (int k = 0; k < 7; k++) {
                    float4 av = a4[k];
                    zacc[4*k+0] += xv * av.x;
                    zacc[4*k+1] += xv * av.y;
                    zacc[4*k+2] += xv * av.z;
                    zacc[4*k+3] += xv * av.w;
                }
            }
            float* zrow = zs + c*XSTR + t*VV;
            #pragma unroll
            for (int w = 0; w < VV; w++) zrow[w] = zacc[w];
        }
        __syncthreads();

        // ---- stage 2: acc[o][tw] += sum_c W[a,o,c] * zs[c][tw] ----
        const float* wbase = Wt + a*4096 + og;
        #pragma unroll 2
        for (int c = 0; c < CC; c++) {
            float4 w0 = *(const float4*)(wbase + c*64);
            float4 w1 = *(const float4*)(wbase + c*64 + 4);
            const float* zrow = zs + c*XSTR + twb;
            float4 z0 = *(const float4*)(zrow);
            float4 z1 = *(const float4*)(zrow + 4);
            float wv[8] = {w0.x,w0.y,w0.z,w0.w,w1.x,w1.y,w1.z,w1.w};
            float zv[8] = {z0.x,z0.y,z0.z,z0.w,z1.x,z1.y,z1.z,z1.w};
            #pragma unroll
            for (int oi = 0; oi < 8; oi++)
                #pragma unroll
                for (int wi = 0; wi < 8; wi++)
                    acc[oi][wi] += wv[oi] * zv[wi];
        }
        __syncthreads();
    }

    // ---- epilogue: store pre-BN y, accumulate per-channel sum/sumsq ----
    // Note: warp (tid>>5) exclusively owns channels [og, og+8), so lane 0 can
    // atomically commit the warp-reduced stats without cross-warp reduction.
    float* ybase = g_y + (size_t)(n*OO)*7500 + (size_t)tb*TWC;
    #pragma unroll
    for (int oi = 0; oi < 8; oi++) {
        int o = og + oi;
        float s = 0.f, sq = 0.f;
        #pragma unroll
        for (int wi = 0; wi < 8; wi++) {
            int tw = twb + wi;
            if (tw < TWC) {
                float v = acc[oi][wi];
                ybase[(size_t)o*7500 + tw] = v;
                s  += v;
                sq += v * v;
            }
        }
        #pragma unroll
        for (int off = 16; off; off >>= 1) {
            s  += __shfl_xor_sync(0xFFFFFFFFu, s,  off);
            sq += __shfl_xor_sync(0xFFFFFFFFu, sq, off);
        }
        if ((tid & 31) == 0) {
            atomicAdd(&g_sum[o],   s);
            atomicAdd(&g_sumsq[o], sq);
        }
    }
}

__global__ void finalize_stats_kernel(const float* __restrict__ gamma,
                                      const float* __restrict__ beta)
{
    int o = threadIdx.x;
    float inv_n = 1.0f / (float)NTOT;
    float mean = g_sum[o] * inv_n;
    float var  = g_sumsq[o] * inv_n - mean * mean;
    float sc   = gamma[o] * rsqrtf(var + 1e-5f);
    g_scale[o] = sc;
    g_shift[o] = beta[o] - mean * sc;
}

__global__ __launch_bounds__(256) void apply_kernel(float* __restrict__ out)
{
    int no = blockIdx.x;                 // n*64 + o
    int o  = no & 63;
    float sc = g_scale[o];
    float sh = g_shift[o];
    const float4* src = (const float4*)(g_y + (size_t)no*7500);
    float4*       dst = (float4*)(out + (size_t)no*7500);
    for (int i = threadIdx.x; i < 7500/4; i += 256) {
        float4 v = src[i];
        v.x = fmaxf(fmaf(v.x, sc, sh), 0.f);
        v.y = fmaxf(fmaf(v.y, sc, sh), 0.f);
        v.z = fmaxf(fmaf(v.z, sc, sh), 0.f);
        v.w = fmaxf(fmaf(v.w, sc, sh), 0.f);
        dst[i] = v;
    }
}

extern "C" void kernel_launch(void* const* d_in, const int* in_sizes, int n_in,
                              void* d_out, int out_size)
{
    const float* x     = (const float*)d_in[0];
    const float* A     = (const float*)d_in[1];
    const float* W     = (const float*)d_in[2];
    // d_in[3] = b: provably cancelled by training-mode BatchNorm mean subtraction
    const float* gamma = (const float*)d_in[4];
    const float* beta  = (const float*)d_in[5];
    float* out = (float*)d_out;

    const size_t smem_bytes =
        (size_t)(NA*APITCH + NA*4096 + 2*CC*XSTR) * sizeof(float); // ~190.7 KB
    cudaFuncSetAttribute(compute_kernel,
                         cudaFuncAttributeMaxDynamicSharedMemorySize,
                         (int)smem_bytes);

    zero_stats_kernel<<<1, OO>>>();
    compute_kernel<<<dim3(TP/TT, NN), 256, smem_bytes>>>(x, A, W);
    finalize_stats_kernel<<<1, OO>>>(gamma, beta);
    apply_kernel<<<NN*OO, 256>>>(out);
}

// round 4
// speedup vs baseline: 1.0469x; 1.0469x over previous
#include <cuda_runtime.h>

// Problem constants
#define NN   64
#define CC   64
#define TP   300
#define VV   25
#define OO   64
#define NA   3
#define TT   10            // t-rows per block tile
#define TWC  250           // TT*VV columns per tile
#define XSTR 260           // padded smem row stride (mult of 4, not mult of 32)
#define ASTR 28            // padded A row (mult of 4)
#define APITCH (VV*ASTR)   // 700
#define NTOT (64*300*25)   // elements per channel for BN stats

typedef unsigned long long u64;

// ---- packed f32x2 helpers (ptxas never emits FFMA2 from C++) ----
__device__ __forceinline__ u64 pack2(float lo, float hi) {
    u64 r; asm("mov.b64 %0, {%1, %2};" : "=l"(r) : "f"(lo), "f"(hi)); return r;
}
__device__ __forceinline__ void unpack2(u64 v, float& lo, float& hi) {
    asm("mov.b64 {%0, %1}, %2;" : "=f"(lo), "=f"(hi) : "l"(v));
}
__device__ __forceinline__ void fma2(u64& d, u64 a, u64 b) {
    asm("fma.rn.f32x2 %0, %1, %2, %0;" : "+l"(d) : "l"(a), "l"(b));
}

// Scratch (static device allocations are the sanctioned workaround)
__device__ float g_y[(size_t)NN*OO*TP*VV];   // pre-BN activations, 122.88 MB
__device__ float g_sum[OO];
__device__ float g_sumsq[OO];
__device__ float g_scale[OO];
__device__ float g_shift[OO];

__global__ void zero_stats_kernel() {
    g_sum[threadIdx.x]   = 0.f;
    g_sumsq[threadIdx.x] = 0.f;
}

__global__ __launch_bounds__(256) void compute_kernel(
    const float* __restrict__ x,
    const float* __restrict__ A,
    const float* __restrict__ W)
{
    extern __shared__ float smem[];
    float* As = smem;                    // NA*APITCH = 2100 floats (zero-padded rows)
    float* Wt = As + NA*APITCH;          // 12288 floats, [a][c][o]
    float* xs = Wt + NA*4096;            // CC*XSTR
    float* zs = xs + CC*XSTR;            // CC*XSTR

    const int tid = threadIdx.x;
    const int tb  = blockIdx.x;          // 0..29 (t tile)
    const int n   = blockIdx.y;          // 0..63

    // Load A with row padding (pad cols 25..27 = 0)
    for (int i = tid; i < NA*APITCH; i += 256) {
        int a = i / APITCH; int r = i - a*APITCH;
        int v = r / ASTR;   int w = r - v*ASTR;
        As[i] = (w < VV) ? A[(a*VV + v)*VV + w] : 0.f;
    }
    // Load W transposed: Wt[a][c][o] = W[a][o][c]
    for (int i = tid; i < NA*4096; i += 256) {
        int a = i >> 12; int r = i & 4095;
        int c = r >> 6;  int o = r & 63;
        Wt[i] = W[a*4096 + o*64 + c];
    }
    // Load x tile: xs[c][tw], tw = t_local*25 + v
    {
        const float* xsrc = x + (size_t)(n*CC)*7500 + (size_t)tb*TWC;
        for (int i = tid; i < CC*TWC; i += 256) {
            int c = i / TWC; int r = i - c*TWC;
            xs[c*XSTR + r] = xsrc[(size_t)c*7500 + r];
        }
    }
    // Zero zs tail columns [250, 260) (stage-2 float4 reads touch up to 255;
    // their products are exactly 0 so stats loops need no guard)
    for (int i = tid; i < CC*(XSTR-TWC); i += 256) {
        int c = i / (XSTR-TWC); int r = i - c*(XSTR-TWC);
        zs[c*XSTR + TWC + r] = 0.f;
    }
    __syncthreads();

    const int og  = (tid >> 5) << 3;     // 8-o group (shared across the warp)
    const int twb = (tid & 31) << 3;     // 8-tw group
    const int lane = tid & 31;

    // acc2[wi][op]: f32x2 pairs over adjacent o (o = og+2*op {+1})
    u64 acc2[8][4];
    #pragma unroll
    for (int i = 0; i < 8; i++)
        #pragma unroll
        for (int j = 0; j < 4; j++) acc2[i][j] = 0ull;

    for (int a = 0; a < NA; a++) {
        // ---- stage 1: zs[c][t*25+w] = sum_v xs[c][t*25+v] * A[a][v][w] ----
        for (int p = tid; p < CC*TT; p += 256) {
            int c = p / TT; int t = p - c*TT;
            const float* xrow = xs + c*XSTR + t*VV;
            u64 zacc[14];
            #pragma unroll
            for (int k = 0; k < 14; k++) zacc[k] = 0ull;
            #pragma unroll 5
            for (int v = 0; v < VV; v++) {
                float xv = xrow[v];
                u64 xv2 = pack2(xv, xv);
                const ulonglong2* a2 = (const ulonglong2*)(As + a*APITCH + v*ASTR);
                #pragma unroll
                for (int k = 0; k < 7; k++) {
                    ulonglong2 av = a2[k];
                    fma2(zacc[2*k],   xv2, av.x);
                    fma2(zacc[2*k+1], xv2, av.y);
                }
            }
            float* zrow = zs + c*XSTR + t*VV;
            float zf[28];
            #pragma unroll
            for (int k = 0; k < 14; k++) unpack2(zacc[k], zf[2*k], zf[2*k+1]);
            #pragma unroll
            for (int w = 0; w < VV; w++) zrow[w] = zf[w];
        }
        __syncthreads();

        // ---- stage 2: acc += W[a,o,c] * zs[c][tw] (f32x2 over o-pairs) ----
        const float* wbase = Wt + a*4096 + og;
        #pragma unroll 4
        for (int c = 0; c < CC; c++) {
            ulonglong2 wA = *(const ulonglong2*)(wbase + c*64);
            ulonglong2 wB = *(const ulonglong2*)(wbase + c*64 + 4);
            u64 wp[4] = {wA.x, wA.y, wB.x, wB.y};
            const float* zrow = zs + c*XSTR + twb;
            float4 z0 = *(const float4*)(zrow);
            float4 z1 = *(const float4*)(zrow + 4);
            u64 zd[8];
            zd[0] = pack2(z0.x, z0.x); zd[1] = pack2(z0.y, z0.y);
            zd[2] = pack2(z0.z, z0.z); zd[3] = pack2(z0.w, z0.w);
            zd[4] = pack2(z1.x, z1.x); zd[5] = pack2(z1.y, z1.y);
            zd[6] = pack2(z1.z, z1.z); zd[7] = pack2(z1.w, z1.w);
            #pragma unroll
            for (int wi = 0; wi < 8; wi++)
                #pragma unroll
                for (int op = 0; op < 4; op++)
                    fma2(acc2[wi][op], wp[op], zd[wi]);
        }
        __syncthreads();
    }

    // ---- epilogue: store pre-BN y (vectorized), accumulate stats ----
    // Warp (tid>>5) exclusively owns channels [og, og+8).
    // Tail columns (tw>=250) hold exact zeros -> stats sums need no guard,
    // but stores must not spill into the next tile's region.
    float* ybase = g_y + (size_t)(n*OO)*7500 + (size_t)tb*TWC;
    #pragma unroll
    for (int op = 0; op < 4; op++) {
        float e[8], f[8];
        #pragma unroll
        for (int wi = 0; wi < 8; wi++) unpack2(acc2[wi][op], e[wi], f[wi]);

        #pragma unroll
        for (int half = 0; half < 2; half++) {
            const float* yv = half ? f : e;
            int o = og + 2*op + half;
            float s = 0.f, sq = 0.f;
            #pragma unroll
            for (int wi = 0; wi < 8; wi++) { s += yv[wi]; sq += yv[wi]*yv[wi]; }

            float* dst = ybase + (size_t)o*7500 + twb;
            if (lane < 31) {
                // 4x STG.64 (16B alignment unavailable: tile offset 1000B)
                *(float2*)(dst)     = make_float2(yv[0], yv[1]);
                *(float2*)(dst + 2) = make_float2(yv[2], yv[3]);
                *(float2*)(dst + 4) = make_float2(yv[4], yv[5]);
                *(float2*)(dst + 6) = make_float2(yv[6], yv[7]);
            } else {
                // lane 31 owns tw 248..255 but only 248,249 are in-tile
                *(float2*)(dst)     = make_float2(yv[0], yv[1]);
            }

            #pragma unroll
            for (int off = 16; off; off >>= 1) {
                s  += __shfl_xor_sync(0xFFFFFFFFu, s,  off);
                sq += __shfl_xor_sync(0xFFFFFFFFu, sq, off);
            }
            if (lane == 0) {
                atomicAdd(&g_sum[o],   s);
                atomicAdd(&g_sumsq[o], sq);
            }
        }
    }
}

__global__ void finalize_stats_kernel(const float* __restrict__ gamma,
                                      const float* __restrict__ beta)
{
    int o = threadIdx.x;
    float inv_n = 1.0f / (float)NTOT;
    float mean = g_sum[o] * inv_n;
    float var  = g_sumsq[o] * inv_n - mean * mean;
    float sc   = gamma[o] * rsqrtf(var + 1e-5f);
    g_scale[o] = sc;
    g_shift[o] = beta[o] - mean * sc;
}

__global__ __launch_bounds__(256) void apply_kernel(float* __restrict__ out)
{
    int no = blockIdx.x;                 // n*64 + o
    int o  = no & 63;
    float sc = g_scale[o];
    float sh = g_shift[o];
    const float4* src = (const float4*)(g_y + (size_t)no*7500);
    float4*       dst = (float4*)(out + (size_t)no*7500);
    for (int i = threadIdx.x; i < 7500/4; i += 256) {
        float4 v = src[i];
        v.x = fmaxf(fmaf(v.x, sc, sh), 0.f);
        v.y = fmaxf(fmaf(v.y, sc, sh), 0.f);
        v.z = fmaxf(fmaf(v.z, sc, sh), 0.f);
        v.w = fmaxf(fmaf(v.w, sc, sh), 0.f);
        dst[i] = v;
    }
}

extern "C" void kernel_launch(void* const* d_in, const int* in_sizes, int n_in,
                              void* d_out, int out_size)
{
    const float* x     = (const float*)d_in[0];
    const float* A     = (const float*)d_in[1];
    const float* W     = (const float*)d_in[2];
    // d_in[3] = b: cancelled exactly by training-mode BatchNorm mean subtraction
    const float* gamma = (const float*)d_in[4];
    const float* beta  = (const float*)d_in[5];
    float* out = (float*)d_out;

    const size_t smem_bytes =
        (size_t)(NA*APITCH + NA*4096 + 2*CC*XSTR) * sizeof(float); // ~190.7 KB
    cudaFuncSetAttribute(compute_kernel,
                         cudaFuncAttributeMaxDynamicSharedMemorySize,
                         (int)smem_bytes);

    zero_stats_kernel<<<1, OO>>>();
    compute_kernel<<<dim3(TP/TT, NN), 256, smem_bytes>>>(x, A, W);
    finalize_stats_kernel<<<1, OO>>>(gamma, beta);
    apply_kernel<<<NN*OO, 256>>>(out);
}